// round 6
// baseline (speedup 1.0000x reference)
#include <cuda_runtime.h>
#include <cuda_bf16.h>

#define NUM_CLASSES 1024
#define FEAT_DIM    512
#define ALPHA       0.5f
#define SORT_THREADS 1024
#define MAIN_WARPS   8
#define MAIN_THREADS (MAIN_WARPS * 32)   // 256
#define MAX_BATCH   16384

// Scratch (no allocations allowed): class counts, exclusive offsets, sorted index list.
__device__ int g_counts[NUM_CLASSES];
__device__ int g_offsets[NUM_CLASSES];
__device__ int g_idx[MAX_BATCH];

// ---------------------------------------------------------------------------
// Kernel 1: single-block counting sort of sample indices by class.
//   - smem histogram of labels (4 labels in flight per thread -> MLP=4)
//   - hierarchical warp-shuffle exclusive scan over 1024 counts (3 barriers)
//   - scatter b -> g_idx[offset[label]+rank] via smem cursors (batched loads)
// ---------------------------------------------------------------------------
__global__ void __launch_bounds__(SORT_THREADS, 1)
sort_by_class_kernel(const int* __restrict__ labels, int B)
{
    __shared__ int s_cnt[NUM_CLASSES];     // histogram, then scatter cursors
    __shared__ int s_wsum[32];             // per-warp totals
    const int t    = threadIdx.x;
    const int warp = t >> 5;
    const int lane = t & 31;

    s_cnt[t] = 0;
    __syncthreads();

    // histogram: batch 4 independent label loads per trip
    {
        int i = t;
        const int stride = SORT_THREADS;
        for (; i + 3 * stride < B; i += 4 * stride) {
            int l0 = __ldg(labels + i);
            int l1 = __ldg(labels + i + stride);
            int l2 = __ldg(labels + i + 2 * stride);
            int l3 = __ldg(labels + i + 3 * stride);
            atomicAdd(&s_cnt[l0], 1);
            atomicAdd(&s_cnt[l1], 1);
            atomicAdd(&s_cnt[l2], 1);
            atomicAdd(&s_cnt[l3], 1);
        }
        for (; i < B; i += stride)
            atomicAdd(&s_cnt[__ldg(labels + i)], 1);
    }
    __syncthreads();

    // hierarchical exclusive scan of s_cnt[0..1023]
    const int v = s_cnt[t];

    // 1) inclusive scan within warp
    int incl = v;
    #pragma unroll
    for (int off = 1; off < 32; off <<= 1) {
        int x = __shfl_up_sync(0xFFFFFFFFu, incl, off);
        if (lane >= off) incl += x;
    }
    if (lane == 31) s_wsum[warp] = incl;
    __syncthreads();

    // 2) warp 0 scans the 32 warp totals (exclusive)
    if (warp == 0) {
        int wv = s_wsum[lane];
        int wincl = wv;
        #pragma unroll
        for (int off = 1; off < 32; off <<= 1) {
            int x = __shfl_up_sync(0xFFFFFFFFu, wincl, off);
            if (lane >= off) wincl += x;
        }
        s_wsum[lane] = wincl - wv;   // exclusive warp base
    }
    __syncthreads();

    // 3) combine: exclusive prefix for this class
    const int excl = s_wsum[warp] + (incl - v);
    g_counts[t]  = v;
    g_offsets[t] = excl;

    // reuse s_cnt as scatter cursors
    s_cnt[t] = excl;
    __syncthreads();

    // scatter sample indices, 4 labels in flight per trip.
    // (order within a class is atomic-race order; only perturbs FP summation
    //  order downstream, << 1e-3 rel-err)
    {
        int i = t;
        const int stride = SORT_THREADS;
        for (; i + 3 * stride < B; i += 4 * stride) {
            int l0 = __ldg(labels + i);
            int l1 = __ldg(labels + i + stride);
            int l2 = __ldg(labels + i + 2 * stride);
            int l3 = __ldg(labels + i + 3 * stride);
            int p0 = atomicAdd(&s_cnt[l0], 1);
            int p1 = atomicAdd(&s_cnt[l1], 1);
            int p2 = atomicAdd(&s_cnt[l2], 1);
            int p3 = atomicAdd(&s_cnt[l3], 1);
            g_idx[p0] = i;
            g_idx[p1] = i + stride;
            g_idx[p2] = i + 2 * stride;
            g_idx[p3] = i + 3 * stride;
        }
        for (; i < B; i += stride) {
            int lab = __ldg(labels + i);
            int p = atomicAdd(&s_cnt[lab], 1);
            g_idx[p] = i;
        }
    }
}

// ---------------------------------------------------------------------------
// Kernel 2: one block per class. Fused:
//   result[b]       = ||features[b] - centers[c]||^2   (b in class c)
//   new_centers[c]  = centers[c] - ALPHA*(cnt*centers[c] - sum_f)/(cnt+1)
// 8 warps; warp w handles samples w, w+8, w+16, ... of its class.
// Feature row read exactly once (float4, coalesced), serving both outputs.
// The next sample index is prefetched so g_idx latency overlaps the current
// feature-row loads (removes a serial LDG from the per-iteration chain).
// ---------------------------------------------------------------------------
__global__ void __launch_bounds__(MAIN_THREADS)
center_loss_main_kernel(const float* __restrict__ features,
                        const float* __restrict__ centers,
                        float* __restrict__ result,
                        float* __restrict__ new_centers)
{
    const int c    = blockIdx.x;
    const int tid  = threadIdx.x;
    const int warp = tid >> 5;
    const int lane = tid & 31;

    __shared__ float4 s_cen[FEAT_DIM / 4];                  // 2 KB
    __shared__ float4 s_part[MAIN_WARPS][FEAT_DIM / 4];     // 16 KB

    // load this class's center row (128 float4 = 512 floats)
    const float4* crow = reinterpret_cast<const float4*>(centers + (size_t)c * FEAT_DIM);
    if (tid < FEAT_DIM / 4) {
        s_cen[tid] = crow[tid];
    }
    __syncthreads();

    const int start = __ldg(&g_offsets[c]);
    const int cnt   = __ldg(&g_counts[c]);

    // per-warp feature-sum accumulators: 4 chunks of 128 floats (float4/lane)
    float4 acc0 = make_float4(0.f, 0.f, 0.f, 0.f);
    float4 acc1 = acc0, acc2 = acc0, acc3 = acc0;

    // software-pipelined index fetch
    int s = warp;
    int b = (s < cnt) ? __ldg(&g_idx[start + s]) : 0;

    while (s < cnt) {
        const int s_next = s + MAIN_WARPS;
        // prefetch next index; overlaps with this trip's feature loads
        const int b_next = (s_next < cnt) ? __ldg(&g_idx[start + s_next]) : 0;

        const float4* frow = reinterpret_cast<const float4*>(features + (size_t)b * FEAT_DIM);

        // issue all 4 loads up front (MLP=4)
        float4 f0 = frow[0 * 32 + lane];
        float4 f1 = frow[1 * 32 + lane];
        float4 f2 = frow[2 * 32 + lane];
        float4 f3 = frow[3 * 32 + lane];

        float dist = 0.f;
        {
            float4 cv = s_cen[0 * 32 + lane];
            float dx = f0.x - cv.x, dy = f0.y - cv.y, dz = f0.z - cv.z, dw = f0.w - cv.w;
            dist += dx * dx + dy * dy + dz * dz + dw * dw;
            acc0.x += f0.x; acc0.y += f0.y; acc0.z += f0.z; acc0.w += f0.w;
        }
        {
            float4 cv = s_cen[1 * 32 + lane];
            float dx = f1.x - cv.x, dy = f1.y - cv.y, dz = f1.z - cv.z, dw = f1.w - cv.w;
            dist += dx * dx + dy * dy + dz * dz + dw * dw;
            acc1.x += f1.x; acc1.y += f1.y; acc1.z += f1.z; acc1.w += f1.w;
        }
        {
            float4 cv = s_cen[2 * 32 + lane];
            float dx = f2.x - cv.x, dy = f2.y - cv.y, dz = f2.z - cv.z, dw = f2.w - cv.w;
            dist += dx * dx + dy * dy + dz * dz + dw * dw;
            acc2.x += f2.x; acc2.y += f2.y; acc2.z += f2.z; acc2.w += f2.w;
        }
        {
            float4 cv = s_cen[3 * 32 + lane];
            float dx = f3.x - cv.x, dy = f3.y - cv.y, dz = f3.z - cv.z, dw = f3.w - cv.w;
            dist += dx * dx + dy * dy + dz * dz + dw * dw;
            acc3.x += f3.x; acc3.y += f3.y; acc3.z += f3.z; acc3.w += f3.w;
        }

        // warp-level reduce of the squared distance
        #pragma unroll
        for (int off = 16; off > 0; off >>= 1)
            dist += __shfl_xor_sync(0xFFFFFFFFu, dist, off);
        if (lane == 0)
            result[b] = dist;

        s = s_next;
        b = b_next;
    }

    // stash per-warp partial sums
    s_part[warp][0 * 32 + lane] = acc0;
    s_part[warp][1 * 32 + lane] = acc1;
    s_part[warp][2 * 32 + lane] = acc2;
    s_part[warp][3 * 32 + lane] = acc3;
    __syncthreads();

    if (new_centers != nullptr && tid < FEAT_DIM / 4) {
        // combine 8 warp partials for this thread's float4 slot, emit new center
        float sx = 0.f, sy = 0.f, sz = 0.f, sw = 0.f;
        #pragma unroll
        for (int w = 0; w < MAIN_WARPS; w++) {
            float4 p = s_part[w][tid];
            sx += p.x; sy += p.y; sz += p.z; sw += p.w;
        }

        const float4 cv = s_cen[tid];
        const float fcnt = (float)cnt;
        const float scale = ALPHA / (fcnt + 1.0f);
        float4 nc;
        nc.x = cv.x - scale * (fcnt * cv.x - sx);
        nc.y = cv.y - scale * (fcnt * cv.y - sy);
        nc.z = cv.z - scale * (fcnt * cv.z - sz);
        nc.w = cv.w - scale * (fcnt * cv.w - sw);
        reinterpret_cast<float4*>(new_centers + (size_t)c * FEAT_DIM)[tid] = nc;
    }
}

extern "C" void kernel_launch(void* const* d_in, const int* in_sizes, int n_in,
                              void* d_out, int out_size)
{
    const float* features = (const float*)d_in[0];  // [B, 512]
    const float* centers  = (const float*)d_in[1];  // [1024, 512]
    const int*   labels   = (const int*)d_in[2];    // [B]
    int B = in_sizes[2];
    if (B > MAX_BATCH) B = MAX_BATCH;

    float* out = (float*)d_out;
    float* result = out;                       // [B, 1] first (reference return order)
    float* new_centers = nullptr;              // then [1024, 512]
    if (out_size >= B + NUM_CLASSES * FEAT_DIM)
        new_centers = out + B;

    sort_by_class_kernel<<<1, SORT_THREADS>>>(labels, B);
    center_loss_main_kernel<<<NUM_CLASSES, MAIN_THREADS>>>(features, centers,
                                                           result, new_centers);
}

// round 11
// speedup vs baseline: 1.2738x; 1.2738x over previous
#include <cuda_runtime.h>
#include <cuda_bf16.h>

#define NUM_CLASSES 1024
#define FEAT_DIM    512
#define ALPHA       0.5f
#define MAIN_WARPS   8
#define MAIN_THREADS (MAIN_WARPS * 32)   // 256
#define LIST_CAP    1024                  // per-class sample list bound (mean 16)

// ---------------------------------------------------------------------------
// Fully fused kernel: one block per class.
//  Phase 1: scan ALL labels (64KB, int4, L1/L2-resident) and collect this
//           class's sample indices into a smem list (warp-aggregated push).
//  Phase 2: balanced 8-warp pass over the list:
//           result[b]      = ||features[b] - centers[c]||^2
//           new_centers[c] = centers[c] - ALPHA*(cnt*centers[c]-sum_f)/(cnt+1)
//  Feature rows are streamed with __ldcs (evict-first) so labels stay cached.
// ---------------------------------------------------------------------------
__global__ void __launch_bounds__(MAIN_THREADS)
center_loss_fused_kernel(const float* __restrict__ features,
                         const float* __restrict__ centers,
                         const int*   __restrict__ labels,
                         int B,
                         float* __restrict__ result,
                         float* __restrict__ new_centers)
{
    const int c    = blockIdx.x;
    const int tid  = threadIdx.x;
    const int warp = tid >> 5;
    const int lane = tid & 31;

    __shared__ float4 s_cen[FEAT_DIM / 4];                  // 2 KB
    __shared__ float4 s_part[MAIN_WARPS][FEAT_DIM / 4];     // 16 KB
    __shared__ int    s_list[LIST_CAP];                     // 4 KB
    __shared__ int    s_cnt;

    // load this class's center row (128 float4)
    const float4* crow = reinterpret_cast<const float4*>(centers + (size_t)c * FEAT_DIM);
    if (tid < FEAT_DIM / 4)
        s_cen[tid] = __ldg(crow + tid);
    if (tid == 0)
        s_cnt = 0;
    __syncthreads();

    // ---------------- Phase 1: label scan -> smem index list ----------------
    // Warp-aggregated push: ballot each of the 4 lane-predicates, one atomic
    // per warp per hit-mask, lane rank via popc of lower-lane bits.
    {
        const int4* lab4 = reinterpret_cast<const int4*>(labels);
        const int n4 = B >> 2;
        #pragma unroll 4
        for (int i = tid; i < n4; i += MAIN_THREADS) {
            int4 L = __ldg(lab4 + i);
            const int base = i << 2;

            #pragma unroll
            for (int k = 0; k < 4; k++) {
                const int lab = (k == 0) ? L.x : (k == 1) ? L.y : (k == 2) ? L.z : L.w;
                const bool hit = (lab == c);
                const unsigned m = __ballot_sync(0xFFFFFFFFu, hit);
                if (m) {
                    int basep = 0;
                    const int leader = __ffs(m) - 1;
                    if (lane == leader)
                        basep = atomicAdd(&s_cnt, __popc(m));
                    basep = __shfl_sync(0xFFFFFFFFu, basep, leader);
                    if (hit) {
                        const int p = basep + __popc(m & ((1u << lane) - 1u));
                        if (p < LIST_CAP) s_list[p] = base + k;
                    }
                }
            }
        }
        // tail (B not multiple of 4)
        for (int i = (n4 << 2) + tid; i < B; i += MAIN_THREADS) {
            if (__ldg(labels + i) == c) {
                int p = atomicAdd(&s_cnt, 1);
                if (p < LIST_CAP) s_list[p] = i;
            }
        }
    }
    __syncthreads();

    int cnt = s_cnt;
    if (cnt > LIST_CAP) cnt = LIST_CAP;

    // ---------------- Phase 2: balanced per-class pass ----------------------
    // per-warp feature-sum accumulators: 4 chunks of 128 floats (float4/lane)
    float4 acc0 = make_float4(0.f, 0.f, 0.f, 0.f);
    float4 acc1 = acc0, acc2 = acc0, acc3 = acc0;

    for (int s = warp; s < cnt; s += MAIN_WARPS) {
        const int b = s_list[s];
        const float4* frow = reinterpret_cast<const float4*>(features + (size_t)b * FEAT_DIM);

        // issue all 4 row-chunk loads up front (MLP=4), streaming (evict-first)
        float4 f0 = __ldcs(frow + 0 * 32 + lane);
        float4 f1 = __ldcs(frow + 1 * 32 + lane);
        float4 f2 = __ldcs(frow + 2 * 32 + lane);
        float4 f3 = __ldcs(frow + 3 * 32 + lane);

        float dist = 0.f;
        {
            float4 cv = s_cen[0 * 32 + lane];
            float dx = f0.x - cv.x, dy = f0.y - cv.y, dz = f0.z - cv.z, dw = f0.w - cv.w;
            dist += dx * dx + dy * dy + dz * dz + dw * dw;
            acc0.x += f0.x; acc0.y += f0.y; acc0.z += f0.z; acc0.w += f0.w;
        }
        {
            float4 cv = s_cen[1 * 32 + lane];
            float dx = f1.x - cv.x, dy = f1.y - cv.y, dz = f1.z - cv.z, dw = f1.w - cv.w;
            dist += dx * dx + dy * dy + dz * dz + dw * dw;
            acc1.x += f1.x; acc1.y += f1.y; acc1.z += f1.z; acc1.w += f1.w;
        }
        {
            float4 cv = s_cen[2 * 32 + lane];
            float dx = f2.x - cv.x, dy = f2.y - cv.y, dz = f2.z - cv.z, dw = f2.w - cv.w;
            dist += dx * dx + dy * dy + dz * dz + dw * dw;
            acc2.x += f2.x; acc2.y += f2.y; acc2.z += f2.z; acc2.w += f2.w;
        }
        {
            float4 cv = s_cen[3 * 32 + lane];
            float dx = f3.x - cv.x, dy = f3.y - cv.y, dz = f3.z - cv.z, dw = f3.w - cv.w;
            dist += dx * dx + dy * dy + dz * dz + dw * dw;
            acc3.x += f3.x; acc3.y += f3.y; acc3.z += f3.z; acc3.w += f3.w;
        }

        // warp-level reduce of the squared distance
        #pragma unroll
        for (int off = 16; off > 0; off >>= 1)
            dist += __shfl_xor_sync(0xFFFFFFFFu, dist, off);
        if (lane == 0)
            result[b] = dist;
    }

    // stash per-warp partial sums
    s_part[warp][0 * 32 + lane] = acc0;
    s_part[warp][1 * 32 + lane] = acc1;
    s_part[warp][2 * 32 + lane] = acc2;
    s_part[warp][3 * 32 + lane] = acc3;
    __syncthreads();

    if (new_centers != nullptr && tid < FEAT_DIM / 4) {
        // combine 8 warp partials for this thread's float4 slot, emit new center
        float sx = 0.f, sy = 0.f, sz = 0.f, sw = 0.f;
        #pragma unroll
        for (int w = 0; w < MAIN_WARPS; w++) {
            float4 p = s_part[w][tid];
            sx += p.x; sy += p.y; sz += p.z; sw += p.w;
        }

        const float4 cv = s_cen[tid];
        const float fcnt = (float)cnt;
        const float scale = ALPHA / (fcnt + 1.0f);
        float4 nc;
        nc.x = cv.x - scale * (fcnt * cv.x - sx);
        nc.y = cv.y - scale * (fcnt * cv.y - sy);
        nc.z = cv.z - scale * (fcnt * cv.z - sz);
        nc.w = cv.w - scale * (fcnt * cv.w - sw);
        reinterpret_cast<float4*>(new_centers + (size_t)c * FEAT_DIM)[tid] = nc;
    }
}

extern "C" void kernel_launch(void* const* d_in, const int* in_sizes, int n_in,
                              void* d_out, int out_size)
{
    const float* features = (const float*)d_in[0];  // [B, 512]
    const float* centers  = (const float*)d_in[1];  // [1024, 512]
    const int*   labels   = (const int*)d_in[2];    // [B]
    const int B = in_sizes[2];

    float* out = (float*)d_out;
    float* result = out;                       // [B, 1] first (reference return order)
    float* new_centers = nullptr;              // then [1024, 512]
    if (out_size >= B + NUM_CLASSES * FEAT_DIM)
        new_centers = out + B;

    center_loss_fused_kernel<<<NUM_CLASSES, MAIN_THREADS>>>(features, centers, labels,
                                                            B, result, new_centers);
}